// round 6
// baseline (speedup 1.0000x reference)
#include <cuda_runtime.h>
#include <cuda_fp16.h>

#define BB 256    // batch
#define TT 512    // timesteps

typedef unsigned long long ull;

// ---------------------------------------------------------------------------
// f32x2 packed-math helpers
// ---------------------------------------------------------------------------
__device__ __forceinline__ void ffma2(ull& d, ull a, ull b) {
    asm("fma.rn.f32x2 %0, %1, %2, %0;" : "+l"(d) : "l"(a), "l"(b));
}
__device__ __forceinline__ ull pack2(float x, float y) {
    ull r; asm("mov.b64 %0, {%1, %2};" : "=l"(r) : "f"(x), "f"(y)); return r;
}
__device__ __forceinline__ float2 unpk2(ull v) {
    float2 f; asm("mov.b64 {%0, %1}, %2;" : "=f"(f.x), "=f"(f.y) : "l"(v)); return f;
}
__device__ __forceinline__ ull addx2(ull a, ull b) {
    ull r; asm("add.rn.f32x2 %0, %1, %2;" : "=l"(r) : "l"(a), "l"(b)); return r;
}
// sigmoid via single-MUFU tanh: sig(x) = 0.5*tanh(x/2) + 0.5
__device__ __forceinline__ float sigf(float x) {
    float t;
    asm("tanh.approx.f32 %0, %1;" : "=f"(t) : "f"(0.5f * x));
    return fmaf(t, 0.5f, 0.5f);
}

// Quad-gate select: mine = gate g; p1 = gate g^1; rv = gate g^2; p2 = gate g^3.
__device__ __forceinline__ void quad_select(
    int g, float zm, float p1, float rv, float p2,
    float& zi, float& zf, float& zg, float& zo)
{
    bool lo = g & 1, hi = g & 2;
    zi = hi ? (lo ? p2 : rv) : (lo ? p1 : zm);
    zf = hi ? (lo ? rv : p2) : (lo ? zm : p1);
    zg = hi ? (lo ? p1 : zm) : (lo ? p2 : rv);
    zo = hi ? (lo ? zm : p1) : (lo ? rv : p2);
}

// ---------------------------------------------------------------------------
// Device scratch
// ---------------------------------------------------------------------------
__device__ float g_zx1[TT * BB * 512];   // [T,B,4*128]
__device__ float g_h1 [TT * BB * 128];   // [T,B,128]
__device__ float g_zx2[TT * BB * 256];   // [T,B,4*64]
__device__ float g_h2 [TT * BB * 64];    // [T,B,64]
__device__ float g_zx3[TT * BB * 256];   // [T,B,4*64]
__device__ float g_h3 [BB * 64];         // last-step hidden of layer 3

// ---------------------------------------------------------------------------
// Projection GEMM (f32x2 inner product).
// ---------------------------------------------------------------------------
template<int K, int N, bool GATHER>
__global__ __launch_bounds__(256) void proj_gemm(
    const float* __restrict__ A, const float* __restrict__ W,
    const float* __restrict__ bias, float* __restrict__ C)
{
    constexpr int BM = 128, BN = 128, BK = 8;
    __shared__ float As[BK][BM];
    __shared__ float Ws[BK][BN];

    const int tid = threadIdx.x;
    const int m0  = blockIdx.x * BM;
    const int n0  = blockIdx.y * BN;

    const int arow = tid >> 1;
    const int acol = (tid & 1) << 2;
    const int wk = tid >> 5;
    const int wn = (tid & 31) << 2;

    const float* a_src;
    {
        int mrow = m0 + arow;
        if (GATHER) {
            int b = mrow & (BB - 1);
            int t = mrow >> 8;
            a_src = A + ((long)b * TT + t) * K + acol;
        } else {
            a_src = A + (long)mrow * K + acol;
        }
    }
    const float* w_src = W + (long)wk * N + n0 + wn;

    const int tx = tid & 15;
    const int ty = tid >> 4;

    ull acc2[8][4];
#pragma unroll
    for (int i = 0; i < 8; i++)
#pragma unroll
        for (int j = 0; j < 4; j++) acc2[i][j] = 0ull;

    for (int kt = 0; kt < K; kt += BK) {
        float4 av = *reinterpret_cast<const float4*>(a_src + kt);
        float4 wv = *reinterpret_cast<const float4*>(w_src + (long)kt * N);
        As[acol + 0][arow] = av.x;
        As[acol + 1][arow] = av.y;
        As[acol + 2][arow] = av.z;
        As[acol + 3][arow] = av.w;
        *reinterpret_cast<float4*>(&Ws[wk][wn]) = wv;
        __syncthreads();

#pragma unroll
        for (int k = 0; k < BK; k++) {
            float4 a0 = *reinterpret_cast<const float4*>(&As[k][ty * 8]);
            float4 a1 = *reinterpret_cast<const float4*>(&As[k][ty * 8 + 4]);
            ulonglong2 b0 = *reinterpret_cast<const ulonglong2*>(&Ws[k][tx * 8]);
            ulonglong2 b1 = *reinterpret_cast<const ulonglong2*>(&Ws[k][tx * 8 + 4]);
            ull br[4] = { b0.x, b0.y, b1.x, b1.y };
            float ar[8] = {a0.x, a0.y, a0.z, a0.w, a1.x, a1.y, a1.z, a1.w};
#pragma unroll
            for (int i = 0; i < 8; i++) {
                ull ai = pack2(ar[i], ar[i]);
#pragma unroll
                for (int j = 0; j < 4; j++) ffma2(acc2[i][j], ai, br[j]);
            }
        }
        __syncthreads();
    }

    float bb[8];
#pragma unroll
    for (int j = 0; j < 8; j++) bb[j] = bias[n0 + tx * 8 + j];

#pragma unroll
    for (int i = 0; i < 8; i++) {
        long m = m0 + ty * 8 + i;
        float2 p0 = unpk2(acc2[i][0]);
        float2 p1 = unpk2(acc2[i][1]);
        float2 p2 = unpk2(acc2[i][2]);
        float2 p3 = unpk2(acc2[i][3]);
        float4 o0, o1;
        o0.x = p0.x + bb[0]; o0.y = p0.y + bb[1];
        o0.z = p1.x + bb[2]; o0.w = p1.y + bb[3];
        o1.x = p2.x + bb[4]; o1.y = p2.y + bb[5];
        o1.z = p3.x + bb[6]; o1.w = p3.y + bb[7];
        *reinterpret_cast<float4*>(&C[m * N + n0 + tx * 8])     = o0;
        *reinterpret_cast<float4*>(&C[m * N + n0 + tx * 8 + 4]) = o1;
    }
}

// ---------------------------------------------------------------------------
// Layer-2/3 recurrence: U=64, G=256. 128 CTAs x 256 threads.
// CTA = two INDEPENDENT 128-thread halves; half h owns batch row b0+h,
// its own h_s buffer and its own named barrier (id h+1). Warps of the two
// halves alternate across SMSPs, covering each other's stalls.
// Thread (within half): gate g = htid&3, unit j = htid>>2 (0..31);
// owns gate columns g*64+j and g*64+j+32. Lanes g<2 combine unit j,
// lanes g>=2 combine unit j+32 (c replicated x2).
// ---------------------------------------------------------------------------
template<bool WRITE_ALL>
__global__ __launch_bounds__(256, 1) void lstm64_rec(
    const float* __restrict__ zx,   // [T,B,256]
    const float* __restrict__ Uw,   // [64,256]
    float* __restrict__ h_out)      // [T,B,64] or [B,64]
{
    constexpr int U = 64, G = 256;
    constexpr int PF = 4;
    constexpr long ZSTRIDE = (long)BB * G;
    __shared__ float h_s[2][2][U];  // [buf][half][unit]

    const int tid  = threadIdx.x;
    const int half = tid >> 7;
    const int htid = tid & 127;
    const int g    = htid & 3;
    const int j    = htid >> 2;          // 0..31
    const int cA   = g * U + j;
    const int cB   = g * U + j + 32;
    const int row  = blockIdx.x * 2 + half;
    const int unit = j + ((g & 2) << 4); // j or j+32
    const bool useB = (g & 2) != 0;

    ull wA[32], wB[32];
#pragma unroll
    for (int k2 = 0; k2 < 32; k2++) {
        wA[k2] = pack2(Uw[(2 * k2) * G + cA], Uw[(2 * k2 + 1) * G + cA]);
        wB[k2] = pack2(Uw[(2 * k2) * G + cB], Uw[(2 * k2 + 1) * G + cB]);
    }
    (&h_s[0][0][0])[tid] = 0.f;          // zero both buffers (256 floats)
    __syncthreads();

    const float* zpA = zx + (long)row * G + cA;
    const float* zpB = zx + (long)row * G + cB;

    float creg = 0.f;
    float zAr[PF], zBr[PF];
#pragma unroll
    for (int p = 0; p < PF; p++) {
        zAr[p] = zpA[(long)p * ZSTRIDE];
        zBr[p] = zpB[(long)p * ZSTRIDE];
    }

    int cur = 0;
#pragma unroll 2
    for (int t = 0; t < TT; t++) {
        const int s = t & (PF - 1);
        float zA = zAr[s], zB = zBr[s];
        if (t + PF < TT) {
            zAr[s] = zpA[(long)(t + PF) * ZSTRIDE];
            zBr[s] = zpB[(long)(t + PF) * ZSTRIDE];
        }

        ull aA0 = 0ull, aA1 = 0ull, aB0 = 0ull, aB1 = 0ull;
        const ulonglong2* hp = reinterpret_cast<const ulonglong2*>(&h_s[cur][half][0]);
#pragma unroll
        for (int k4 = 0; k4 < 16; k4++) {
            ulonglong2 hh = hp[k4];
            ffma2(aA0, wA[2 * k4],     hh.x);
            ffma2(aA1, wA[2 * k4 + 1], hh.y);
            ffma2(aB0, wB[2 * k4],     hh.x);
            ffma2(aB1, wB[2 * k4 + 1], hh.y);
        }
        float2 fA = unpk2(addx2(aA0, aA1));
        float2 fB = unpk2(addx2(aB0, aB1));
        zA += fA.x + fA.y;
        zB += fB.x + fB.y;

        // 6 independent butterflies: gates g^1, g^2, g^3 of units j and j+32
        float sA1 = __shfl_xor_sync(0xffffffffu, zA, 1);
        float sA2 = __shfl_xor_sync(0xffffffffu, zA, 2);
        float sA3 = __shfl_xor_sync(0xffffffffu, zA, 3);
        float sB1 = __shfl_xor_sync(0xffffffffu, zB, 1);
        float sB2 = __shfl_xor_sync(0xffffffffu, zB, 2);
        float sB3 = __shfl_xor_sync(0xffffffffu, zB, 3);

        float mine = useB ? zB  : zA;
        float p1   = useB ? sB1 : sA1;
        float rv   = useB ? sB2 : sA2;
        float p2   = useB ? sB3 : sA3;

        float zi, zf, zg_, zoo;
        quad_select(g, mine, p1, rv, p2, zi, zf, zg_, zoo);

        float ig = sigf(zi);
        float fg = sigf(zf);
        float gg = fmaxf(zg_, 0.f);
        float og = sigf(zoo);
        creg = fg * creg + ig * gg;
        float h = og * fmaxf(creg, 0.f);

        if ((g & 1) == 0) {              // lanes 0 (unit j) and 2 (unit j+32)
            h_s[cur ^ 1][half][unit] = h;
            if (WRITE_ALL)
                h_out[((long)t * BB + row) * U + unit] = h;
            else if (t == TT - 1)
                h_out[(long)row * U + unit] = h;
        }
        asm volatile("bar.sync %0, 128;" :: "r"(half + 1) : "memory");
        cur ^= 1;
    }
}

// ---------------------------------------------------------------------------
// Layer-1 recurrence: U=128, G=512, 2 rows/CTA, 128 CTAs x 256 threads.
// Thread owns 2 columns (units j, j+64; gate g) and computes both rows.
// fp16 weights in registers, HFMA2 flushed to fp32 every 32 k.
// ---------------------------------------------------------------------------
__global__ __launch_bounds__(256) void lstm1_rec(
    const float* __restrict__ zx,   // [T,B,512]
    const float* __restrict__ Uw,   // [128,512]
    float* __restrict__ h_out)      // [T,B,128]
{
    constexpr int U = 128, G = 512;
    constexpr int PF = 4;
    constexpr long ZSTRIDE = (long)BB * G;
    __shared__ __half h_s[2][2][U];

    const int tid = threadIdx.x;
    const int b0  = blockIdx.x * 2;
    const int g   = tid & 3;
    const int j0  = tid >> 2;           // units j0 and j0+64
    const int c0  = g * U + j0;
    const int c1  = g * U + j0 + 64;
    const int myrow = (g >> 1) & 1;

    half2 w0[U / 2], w1[U / 2];
#pragma unroll
    for (int k2 = 0; k2 < U / 2; k2++) {
        w0[k2] = __floats2half2_rn(Uw[(2 * k2) * G + c0], Uw[(2 * k2 + 1) * G + c0]);
        w1[k2] = __floats2half2_rn(Uw[(2 * k2) * G + c1], Uw[(2 * k2 + 1) * G + c1]);
    }
    for (int i = tid; i < 2 * 2 * U; i += 256)
        (&h_s[0][0][0])[i] = __float2half_rn(0.f);
    __syncthreads();

    const float* z00p = zx + (long)b0 * G + c0;
    const float* z01p = z00p + G;
    const float* z10p = zx + (long)b0 * G + c1;
    const float* z11p = z10p + G;

    float c_a = 0.f, c_b = 0.f;
    float zA0[PF], zA1[PF], zB0[PF], zB1[PF];
#pragma unroll
    for (int p = 0; p < PF; p++) {
        zA0[p] = z00p[(long)p * ZSTRIDE];
        zA1[p] = z01p[(long)p * ZSTRIDE];
        zB0[p] = z10p[(long)p * ZSTRIDE];
        zB1[p] = z11p[(long)p * ZSTRIDE];
    }

    const half2 h2z = __floats2half2_rn(0.f, 0.f);
    int cur = 0;
#pragma unroll 2
    for (int t = 0; t < TT; t++) {
        const int s = t & (PF - 1);
        float a00 = zA0[s], a01 = zA1[s], a10 = zB0[s], a11 = zB1[s];
        if (t + PF < TT) {
            zA0[s] = z00p[(long)(t + PF) * ZSTRIDE];
            zA1[s] = z01p[(long)(t + PF) * ZSTRIDE];
            zB0[s] = z10p[(long)(t + PF) * ZSTRIDE];
            zB1[s] = z11p[(long)(t + PF) * ZSTRIDE];
        }

#pragma unroll
        for (int kb = 0; kb < 4; kb++) {            // 32 k per block
            half2 s00 = h2z, s01 = h2z, s10 = h2z, s11 = h2z;
#pragma unroll
            for (int k8 = 0; k8 < 4; k8++) {        // 8 k per sub-block
                const int kbase = kb * 32 + k8 * 8;
                uint4 hv0 = *reinterpret_cast<const uint4*>(&h_s[cur][0][kbase]);
                uint4 hv1 = *reinterpret_cast<const uint4*>(&h_s[cur][1][kbase]);
                const half2* hp0 = reinterpret_cast<const half2*>(&hv0);
                const half2* hp1 = reinterpret_cast<const half2*>(&hv1);
#pragma unroll
                for (int q = 0; q < 4; q++) {
                    const int k2 = kbase / 2 + q;
                    s00 = __hfma2(w0[k2], hp0[q], s00);
                    s01 = __hfma2(w0[k2], hp1[q], s01);
                    s10 = __hfma2(w1[k2], hp0[q], s10);
                    s11 = __hfma2(w1[k2], hp1[q], s11);
                }
            }
            float2 f;
            f = __half22float2(s00); a00 += f.x + f.y;
            f = __half22float2(s01); a01 += f.x + f.y;
            f = __half22float2(s10); a10 += f.x + f.y;
            f = __half22float2(s11); a11 += f.x + f.y;
        }

        float mineA  = myrow ? a01 : a00;
        float otherA = myrow ? a00 : a01;
        float mineB  = myrow ? a11 : a10;
        float otherB = myrow ? a10 : a11;
        float p1A = __shfl_xor_sync(0xffffffffu, mineA,  1);
        float rvA = __shfl_xor_sync(0xffffffffu, otherA, 2);
        float p2A = __shfl_xor_sync(0xffffffffu, otherA, 3);
        float p1B = __shfl_xor_sync(0xffffffffu, mineB,  1);
        float rvB = __shfl_xor_sync(0xffffffffu, otherB, 2);
        float p2B = __shfl_xor_sync(0xffffffffu, otherB, 3);

        float zi, zf, zg_, zoo;
        quad_select(g, mineA, p1A, rvA, p2A, zi, zf, zg_, zoo);
        float ig = sigf(zi), fg = sigf(zf), og = sigf(zoo);
        c_a = fg * c_a + ig * fmaxf(zg_, 0.f);
        float hA = og * fmaxf(c_a, 0.f);

        quad_select(g, mineB, p1B, rvB, p2B, zi, zf, zg_, zoo);
        ig = sigf(zi); fg = sigf(zf); og = sigf(zoo);
        c_b = fg * c_b + ig * fmaxf(zg_, 0.f);
        float hB = og * fmaxf(c_b, 0.f);

        if ((g & 1) == 0) {
            h_s[cur ^ 1][myrow][j0]      = __float2half_rn(hA);
            h_s[cur ^ 1][myrow][j0 + 64] = __float2half_rn(hB);
            float* ho = h_out + ((long)t * BB + b0 + myrow) * U;
            ho[j0]      = hA;
            ho[j0 + 64] = hB;
        }
        __syncthreads();
        cur ^= 1;
    }
}

// ---------------------------------------------------------------------------
// Dense head
// ---------------------------------------------------------------------------
__global__ __launch_bounds__(256) void dense_kernel(
    const float* __restrict__ h3, const float* __restrict__ Wd1,
    const float* __restrict__ bd1, const float* __restrict__ Wd2,
    const float* __restrict__ bd2, float* __restrict__ out)
{
    __shared__ float w1[64 * 32];
    __shared__ float w2[32];
    __shared__ float b1s[32];
    const int tid = threadIdx.x;
    for (int i = tid; i < 64 * 32; i += 256) w1[i] = Wd1[i];
    if (tid < 32) { w2[tid] = Wd2[tid]; b1s[tid] = bd1[tid]; }
    __syncthreads();

    float hr[64];
#pragma unroll
    for (int k4 = 0; k4 < 16; k4++)
        *reinterpret_cast<float4*>(&hr[4 * k4]) =
            *reinterpret_cast<const float4*>(&h3[tid * 64 + 4 * k4]);

    float o = bd2[0];
#pragma unroll 4
    for (int jj = 0; jj < 32; jj++) {
        float d = b1s[jj];
#pragma unroll
        for (int k = 0; k < 64; k++) d += hr[k] * w1[k * 32 + jj];
        o += fmaxf(d, 0.f) * w2[jj];
    }
    out[tid] = o;
}

// ---------------------------------------------------------------------------
// Launcher
// ---------------------------------------------------------------------------
extern "C" void kernel_launch(void* const* d_in, const int* in_sizes, int n_in,
                              void* d_out, int out_size)
{
    const float* x   = (const float*)d_in[0];
    const float* W1  = (const float*)d_in[1];
    const float* Uw1 = (const float*)d_in[2];
    const float* b1  = (const float*)d_in[3];
    const float* W2  = (const float*)d_in[4];
    const float* Uw2 = (const float*)d_in[5];
    const float* b2  = (const float*)d_in[6];
    const float* W3  = (const float*)d_in[7];
    const float* Uw3 = (const float*)d_in[8];
    const float* b3  = (const float*)d_in[9];
    const float* Wd1 = (const float*)d_in[10];
    const float* bd1 = (const float*)d_in[11];
    const float* Wd2 = (const float*)d_in[12];
    const float* bd2 = (const float*)d_in[13];

    float *zx1, *h1, *zx2, *h2, *zx3, *h3;
    cudaGetSymbolAddress((void**)&zx1, g_zx1);
    cudaGetSymbolAddress((void**)&h1,  g_h1);
    cudaGetSymbolAddress((void**)&zx2, g_zx2);
    cudaGetSymbolAddress((void**)&h2,  g_h2);
    cudaGetSymbolAddress((void**)&zx3, g_zx3);
    cudaGetSymbolAddress((void**)&h3,  g_h3);

    // Layer 1
    proj_gemm<64, 512, true ><<<dim3(1024, 4), 256>>>(x,  W1, b1, zx1);
    lstm1_rec<<<128, 256>>>(zx1, Uw1, h1);
    // Layer 2
    proj_gemm<128, 256, false><<<dim3(1024, 2), 256>>>(h1, W2, b2, zx2);
    lstm64_rec<true ><<<128, 256>>>(zx2, Uw2, h2);
    // Layer 3 (only last hidden step needed)
    proj_gemm<64, 256, false><<<dim3(1024, 2), 256>>>(h2, W3, b3, zx3);
    lstm64_rec<false><<<128, 256>>>(zx3, Uw3, h3);
    // Dense head
    dense_kernel<<<1, 256>>>(h3, Wd1, bd1, Wd2, bd2, (float*)d_out);
}

// round 9
// speedup vs baseline: 1.5069x; 1.5069x over previous
#include <cuda_runtime.h>
#include <cuda_fp16.h>
#include <mma.h>

#define BB 256
#define TT 512

typedef unsigned long long ull;
using namespace nvcuda;

// ---------------- packed-math helpers (all compiled in R5/R6) ----------------
__device__ __forceinline__ void ffma2(ull& d, ull a, ull b) {
    asm("fma.rn.f32x2 %0, %1, %2, %0;" : "+l"(d) : "l"(a), "l"(b));
}
__device__ __forceinline__ ull pack2(float x, float y) {
    ull r; asm("mov.b64 %0, {%1, %2};" : "=l"(r) : "f"(x), "f"(y)); return r;
}
__device__ __forceinline__ float2 unpk2(ull v) {
    float2 f; asm("mov.b64 {%0, %1}, %2;" : "=f"(f.x), "=f"(f.y) : "l"(v)); return f;
}
__device__ __forceinline__ ull addx2(ull a, ull b) {
    ull r; asm("add.rn.f32x2 %0, %1, %2;" : "=l"(r) : "l"(a), "l"(b)); return r;
}
__device__ __forceinline__ float sigf(float x) {
    float t;
    asm("tanh.approx.f32 %0, %1;" : "=f"(t) : "f"(0.5f * x));
    return fmaf(t, 0.5f, 0.5f);
}
__device__ __forceinline__ void quad_select(
    int g, float zm, float p1, float rv, float p2,
    float& zi, float& zf, float& zg, float& zo)
{
    bool lo = (g & 1) != 0;
    bool hi = (g & 2) != 0;
    zi = hi ? (lo ? p2 : rv) : (lo ? p1 : zm);
    zf = hi ? (lo ? rv : p2) : (lo ? zm : p1);
    zg = hi ? (lo ? p1 : zm) : (lo ? p2 : rv);
    zo = hi ? (lo ? zm : p1) : (lo ? rv : p2);
}

// ---------------- device scratch ----------------
__device__ float g_zx1[TT * BB * 512];
__device__ float g_h1 [TT * BB * 128];
__device__ float g_zx2[TT * BB * 256];
__device__ float g_h2 [TT * BB * 64];
__device__ float g_zx3[TT * BB * 256];
__device__ float g_h3 [BB * 64];

// ---------------------------------------------------------------------------
// Tensor-core projection GEMM via wmma (no inline asm).
//   C[m][n] = A_row(m) . W[:,n]   (bias folded into recurrent kernels)
//   fp32 operands split hi+lo fp16; acc = Ahi*Whi + Alo*Whi + Ahi*Wlo.
//   CTA tile 128x128, BK=32, 8 warps (2M x 4N), warp tile 64x32.
//   GATHER: A = x [B,T,F], row m = t*B + b reads x + (b*T+t)*K.
// ---------------------------------------------------------------------------
template<int K, int N, bool GATHER>
__global__ __launch_bounds__(256) void proj_gemm_tc(
    const float* __restrict__ A, const float* __restrict__ W,
    float* __restrict__ C)
{
    const int BM = 128;
    const int BK = 32;
    const int ALD = 48;    // leading dim (halves); 96B rows, 32B-aligned
    const int WLD = 144;   // 288B rows, 32B-aligned

    __shared__ __align__(32) __half As_hi[128 * 48];
    __shared__ __align__(32) __half As_lo[128 * 48];
    __shared__ __align__(32) __half Ws_hi[32 * 144];
    __shared__ __align__(32) __half Ws_lo[32 * 144];

    const int tid  = threadIdx.x;
    const int warp = tid >> 5;
    const int wm   = (warp & 1) * 64;
    const int wn   = (warp >> 1) * 32;
    const int m0   = blockIdx.x * BM;
    const int n0   = blockIdx.y * 128;

    const int arow = tid >> 1;          // 0..127
    const int acol = (tid & 1) * 16;    // 0 or 16
    const float* a_src;
    {
        int mrow = m0 + arow;
        if (GATHER) {
            int b = mrow & (BB - 1);
            int t = mrow >> 8;
            a_src = A + ((long)b * TT + t) * K;
        } else {
            a_src = A + (long)mrow * K;
        }
    }
    const int wrow = tid >> 3;          // 0..31
    const int wcol = (tid & 7) * 16;    // 0..112

    wmma::fragment<wmma::accumulator, 16, 16, 16, float> acc[4][2];
#pragma unroll
    for (int mi = 0; mi < 4; mi++) {
#pragma unroll
        for (int ni = 0; ni < 2; ni++) {
            wmma::fill_fragment(acc[mi][ni], 0.0f);
        }
    }

    for (int kt = 0; kt < K; kt += BK) {
        // A tile: 128 x 32, each thread 16 floats -> hi/lo halves
#pragma unroll
        for (int i4 = 0; i4 < 4; i4++) {
            float4 v = *reinterpret_cast<const float4*>(a_src + kt + acol + i4 * 4);
            float vv[4];
            vv[0] = v.x; vv[1] = v.y; vv[2] = v.z; vv[3] = v.w;
#pragma unroll
            for (int e = 0; e < 4; e++) {
                __half h = __float2half_rn(vv[e]);
                __half l = __float2half_rn(vv[e] - __half2float(h));
                As_hi[arow * ALD + acol + i4 * 4 + e] = h;
                As_lo[arow * ALD + acol + i4 * 4 + e] = l;
            }
        }
        // W tile: 32 x 128
#pragma unroll
        for (int i4 = 0; i4 < 4; i4++) {
            float4 v = *reinterpret_cast<const float4*>(
                W + (long)(kt + wrow) * N + n0 + wcol + i4 * 4);
            float vv[4];
            vv[0] = v.x; vv[1] = v.y; vv[2] = v.z; vv[3] = v.w;
#pragma unroll
            for (int e = 0; e < 4; e++) {
                __half h = __float2half_rn(vv[e]);
                __half l = __float2half_rn(vv[e] - __half2float(h));
                Ws_hi[wrow * WLD + wcol + i4 * 4 + e] = h;
                Ws_lo[wrow * WLD + wcol + i4 * 4 + e] = l;
            }
        }
        __syncthreads();

#pragma unroll
        for (int k16 = 0; k16 < BK / 16; k16++) {
            const int k0 = k16 * 16;
            wmma::fragment<wmma::matrix_a, 16, 16, 16, __half, wmma::row_major> ah[4];
            wmma::fragment<wmma::matrix_a, 16, 16, 16, __half, wmma::row_major> al[4];
            wmma::fragment<wmma::matrix_b, 16, 16, 16, __half, wmma::row_major> bh[2];
            wmma::fragment<wmma::matrix_b, 16, 16, 16, __half, wmma::row_major> bl[2];
#pragma unroll
            for (int mi = 0; mi < 4; mi++) {
                wmma::load_matrix_sync(ah[mi], &As_hi[(wm + mi * 16) * ALD + k0], ALD);
                wmma::load_matrix_sync(al[mi], &As_lo[(wm + mi * 16) * ALD + k0], ALD);
            }
#pragma unroll
            for (int ni = 0; ni < 2; ni++) {
                wmma::load_matrix_sync(bh[ni], &Ws_hi[k0 * WLD + wn + ni * 16], WLD);
                wmma::load_matrix_sync(bl[ni], &Ws_lo[k0 * WLD + wn + ni * 16], WLD);
            }
#pragma unroll
            for (int mi = 0; mi < 4; mi++) {
#pragma unroll
                for (int ni = 0; ni < 2; ni++) {
                    wmma::mma_sync(acc[mi][ni], ah[mi], bh[ni], acc[mi][ni]);
                    wmma::mma_sync(acc[mi][ni], al[mi], bh[ni], acc[mi][ni]);
                    wmma::mma_sync(acc[mi][ni], ah[mi], bl[ni], acc[mi][ni]);
                }
            }
        }
        __syncthreads();
    }

#pragma unroll
    for (int mi = 0; mi < 4; mi++) {
#pragma unroll
        for (int ni = 0; ni < 2; ni++) {
            float* dst = C + (long)(m0 + wm + mi * 16) * N + n0 + wn + ni * 16;
            wmma::store_matrix_sync(dst, acc[mi][ni], N, wmma::mem_row_major);
        }
    }
}

// ---------------------------------------------------------------------------
// Layer-2/3 recurrence: U=64, G=256, 2 rows/CTA, 128 CTAs x 256 threads.
// R5 structure + tanh sigmoid + bias fold.
// ---------------------------------------------------------------------------
template<bool WRITE_ALL>
__global__ __launch_bounds__(256) void lstm64_rec(
    const float* __restrict__ zx,
    const float* __restrict__ Uw,
    const float* __restrict__ bias,
    float* __restrict__ h_out)
{
    const int U = 64;
    const int G = 256;
    const int PF = 4;
    const long ZSTRIDE = (long)BB * G;
    __shared__ float h_s[2][2][64];

    const int tid = threadIdx.x;
    const int b0  = blockIdx.x * 2;
    const int g   = tid & 3;
    const int j   = tid >> 2;
    const int col = g * U + j;
    const int myrow = (g >> 1) & 1;

    ull wr[32];
#pragma unroll
    for (int k2 = 0; k2 < 32; k2++) {
        wr[k2] = pack2(Uw[(2 * k2) * G + col], Uw[(2 * k2 + 1) * G + col]);
    }
    (&h_s[0][0][0])[tid] = 0.f;
    const float bz = bias[col];
    __syncthreads();

    const float* zb0 = zx + (long)b0 * G + col;
    const float* zb1 = zb0 + G;

    float creg = 0.f;
    float zA[4];
    float zB[4];
#pragma unroll
    for (int p = 0; p < PF; p++) {
        zA[p] = zb0[(long)p * ZSTRIDE];
        zB[p] = zb1[(long)p * ZSTRIDE];
    }

    int cur = 0;
#pragma unroll 4
    for (int t = 0; t < TT; t++) {
        const int s = t & (PF - 1);
        float z0 = zA[s] + bz;
        float z1 = zB[s] + bz;
        if (t + PF < TT) {
            zA[s] = zb0[(long)(t + PF) * ZSTRIDE];
            zB[s] = zb1[(long)(t + PF) * ZSTRIDE];
        }

        ull a0a = 0ull;
        ull a0b = 0ull;
        ull a1a = 0ull;
        ull a1b = 0ull;
        const ulonglong2* h0p = reinterpret_cast<const ulonglong2*>(&h_s[cur][0][0]);
        const ulonglong2* h1p = reinterpret_cast<const ulonglong2*>(&h_s[cur][1][0]);
#pragma unroll
        for (int k4 = 0; k4 < 16; k4++) {
            ulonglong2 h0 = h0p[k4];
            ulonglong2 h1 = h1p[k4];
            ffma2(a0a, wr[2 * k4],     h0.x);
            ffma2(a0b, wr[2 * k4 + 1], h0.y);
            ffma2(a1a, wr[2 * k4],     h1.x);
            ffma2(a1b, wr[2 * k4 + 1], h1.y);
        }
        float2 f0 = unpk2(addx2(a0a, a0b));
        float2 f1 = unpk2(addx2(a1a, a1b));
        z0 += f0.x + f0.y;
        z1 += f1.x + f1.y;

        float mine  = myrow ? z1 : z0;
        float other = myrow ? z0 : z1;
        float p1 = __shfl_xor_sync(0xffffffffu, mine,  1);
        float rv = __shfl_xor_sync(0xffffffffu, other, 2);
        float p2 = __shfl_xor_sync(0xffffffffu, other, 3);

        float zi, zf, zg_, zoo;
        quad_select(g, mine, p1, rv, p2, zi, zf, zg_, zoo);

        float ig = sigf(zi);
        float fg = sigf(zf);
        float gg = fmaxf(zg_, 0.f);
        float og = sigf(zoo);
        creg = fg * creg + ig * gg;
        float h = og * fmaxf(creg, 0.f);

        if ((g & 1) == 0) {
            h_s[cur ^ 1][myrow][j] = h;
            if (WRITE_ALL) {
                h_out[((long)t * BB + b0 + myrow) * U + j] = h;
            } else if (t == TT - 1) {
                h_out[(b0 + myrow) * U + j] = h;
            }
        }
        __syncthreads();
        cur ^= 1;
    }
}

// ---------------------------------------------------------------------------
// Layer-1 recurrence: U=128, G=512, 2 rows/CTA, 128 CTAs x 256 threads.
// R5 structure + tanh sigmoid + bias fold.
// ---------------------------------------------------------------------------
__global__ __launch_bounds__(256) void lstm1_rec(
    const float* __restrict__ zx,
    const float* __restrict__ Uw,
    const float* __restrict__ bias,
    float* __restrict__ h_out)
{
    const int U = 128;
    const int G = 512;
    const int PF = 4;
    const long ZSTRIDE = (long)BB * G;
    __shared__ __half h_s[2][2][128];

    const int tid = threadIdx.x;
    const int b0  = blockIdx.x * 2;
    const int g   = tid & 3;
    const int j0  = tid >> 2;
    const int c0  = g * U + j0;
    const int c1  = g * U + j0 + 64;
    const int myrow = (g >> 1) & 1;

    half2 w0[64];
    half2 w1[64];
#pragma unroll
    for (int k2 = 0; k2 < 64; k2++) {
        w0[k2] = __floats2half2_rn(Uw[(2 * k2) * G + c0], Uw[(2 * k2 + 1) * G + c0]);
        w1[k2] = __floats2half2_rn(Uw[(2 * k2) * G + c1], Uw[(2 * k2 + 1) * G + c1]);
    }
    for (int i = tid; i < 512; i += 256) {
        (&h_s[0][0][0])[i] = __float2half_rn(0.f);
    }
    const float bz0 = bias[c0];
    const float bz1 = bias[c1];
    __syncthreads();

    const float* z00p = zx + (long)b0 * G + c0;
    const float* z01p = z00p + G;
    const float* z10p = zx + (long)b0 * G + c1;
    const float* z11p = z10p + G;

    float c_a = 0.f;
    float c_b = 0.f;
    float zA0[4];
    float zA1[4];
    float zB0[4];
    float zB1[4];
#pragma unroll
    for (int p = 0; p < PF; p++) {
        zA0[p] = z00p[(long)p * ZSTRIDE];
        zA1[p] = z01p[(long)p * ZSTRIDE];
        zB0[p] = z10p[(long)p * ZSTRIDE];
        zB1[p] = z11p[(long)p * ZSTRIDE];
    }

    int cur = 0;
#pragma unroll 4
    for (int t = 0; t < TT; t++) {
        const int s = t & (PF - 1);
        float a00 = zA0[s] + bz0;
        float a01 = zA1[s] + bz0;
        float a10 = zB0[s] + bz1;
        float a11 = zB1[s] + bz1;
        if (t + PF < TT) {
            zA0[s] = z00p[(long)(t + PF) * ZSTRIDE];
            zA1[s] = z01p[(long)(t + PF) * ZSTRIDE];
            zB0[s] = z10p[(long)(t + PF) * ZSTRIDE];
            zB1[s] = z11p[(long)(t + PF) * ZSTRIDE];
        }

#pragma unroll
        for (int kb = 0; kb < 4; kb++) {
            half2 s00 = __floats2half2_rn(0.f, 0.f);
            half2 s01 = __floats2half2_rn(0.f, 0.f);
            half2 s10 = __floats2half2_rn(0.f, 0.f);
            half2 s11 = __floats2half2_rn(0.f, 0.f);
#pragma unroll
            for (int k8 = 0; k8 < 4; k8++) {
                const int kbase = kb * 32 + k8 * 8;
                uint4 hv0 = *reinterpret_cast<const uint4*>(&h_s[cur][0][kbase]);
                uint4 hv1 = *reinterpret_cast<const uint4*>(&h_s[cur][1][kbase]);
                const half2* hp0 = reinterpret_cast<const half2*>(&hv0);
                const half2* hp1 = reinterpret_cast<const half2*>(&hv1);
#pragma unroll
                for (int q = 0; q < 4; q++) {
                    const int k2 = kbase / 2 + q;
                    s00 = __hfma2(w0[k2], hp0[q], s00);
                    s01 = __hfma2(w0[k2], hp1[q], s01);
                    s10 = __hfma2(w1[k2], hp0[q], s10);
                    s11 = __hfma2(w1[k2], hp1[q], s11);
                }
            }
            float2 fa = __half22float2(s00);
            float2 fb = __half22float2(s01);
            float2 fc = __half22float2(s10);
            float2 fd = __half22float2(s11);
            a00 += fa.x + fa.y;
            a01 += fb.x + fb.y;
            a10 += fc.x + fc.y;
            a11 += fd.x + fd.y;
        }

        float mineA  = myrow ? a01 : a00;
        float otherA = myrow ? a00 : a01;
        float mineB  = myrow ? a11 : a10;
        float otherB = myrow ? a10 : a11;
        float p1A = __shfl_xor_sync(0xffffffffu, mineA,  1);
        float rvA = __shfl_xor_sync(0xffffffffu, otherA, 2);
        float p2A = __shfl_xor_sync(0xffffffffu, otherA, 3);
        float p1B = __shfl_xor_sync(0xffffffffu, mineB,  1);
        float rvB = __shfl_xor_sync(0xffffffffu, otherB, 2);
        float p2B = __shfl_xor_sync(0xffffffffu, otherB, 3);

        float zi, zf, zg_, zoo;
        quad_select(g, mineA, p1A, rvA, p2A, zi, zf, zg_, zoo);
        float ig = sigf(zi);
        float fg = sigf(zf);
        float og = sigf(zoo);
        c_a = fg * c_a + ig * fmaxf(zg_, 0.f);
        float hA = og * fmaxf(c_a, 0.f);

        quad_select(g, mineB, p1B, rvB, p2B, zi, zf, zg_, zoo);
        ig = sigf(zi);
        fg = sigf(zf);
        og = sigf(zoo);
        c_b = fg * c_b + ig * fmaxf(zg_, 0.f);
        float hB = og * fmaxf(c_b, 0.f);

        if ((g & 1) == 0) {
            h_s[cur ^ 1][myrow][j0]      = __float2half_rn(hA);
            h_s[cur ^ 1][myrow][j0 + 64] = __float2half_rn(hB);
            float* ho = h_out + ((long)t * BB + b0 + myrow) * U;
            ho[j0]      = hA;
            ho[j0 + 64] = hB;
        }
        __syncthreads();
        cur ^= 1;
    }
}

// ---------------- dense head ----------------
__global__ __launch_bounds__(256) void dense_kernel(
    const float* __restrict__ h3, const float* __restrict__ Wd1,
    const float* __restrict__ bd1, const float* __restrict__ Wd2,
    const float* __restrict__ bd2, float* __restrict__ out)
{
    __shared__ float w1[64 * 32];
    __shared__ float w2[32];
    __shared__ float b1s[32];
    const int tid = threadIdx.x;
    for (int i = tid; i < 64 * 32; i += 256) {
        w1[i] = Wd1[i];
    }
    if (tid < 32) {
        w2[tid] = Wd2[tid];
        b1s[tid] = bd1[tid];
    }
    __syncthreads();

    float hr[64];
#pragma unroll
    for (int k4 = 0; k4 < 16; k4++) {
        *reinterpret_cast<float4*>(&hr[4 * k4]) =
            *reinterpret_cast<const float4*>(&h3[tid * 64 + 4 * k4]);
    }

    float o = bd2[0];
#pragma unroll 4
    for (int jj = 0; jj < 32; jj++) {
        float d = b1s[jj];
#pragma unroll
        for (int k = 0; k < 64; k++) {
            d += hr[k] * w1[k * 32 + jj];
        }
        o += fmaxf(d, 0.f) * w2[jj];
    }
    out[tid] = o;
}

// ---------------- launcher ----------------
extern "C" void kernel_launch(void* const* d_in, const int* in_sizes, int n_in,
                              void* d_out, int out_size)
{
    const float* x   = (const float*)d_in[0];
    const float* W1  = (const float*)d_in[1];
    const float* Uw1 = (const float*)d_in[2];
    const float* b1  = (const float*)d_in[3];
    const float* W2  = (const float*)d_in[4];
    const float* Uw2 = (const float*)d_in[5];
    const float* b2  = (const float*)d_in[6];
    const float* W3  = (const float*)d_in[7];
    const float* Uw3 = (const float*)d_in[8];
    const float* b3  = (const float*)d_in[9];
    const float* Wd1 = (const float*)d_in[10];
    const float* bd1 = (const float*)d_in[11];
    const float* Wd2 = (const float*)d_in[12];
    const float* bd2 = (const float*)d_in[13];

    float* zx1;
    float* h1;
    float* zx2;
    float* h2;
    float* zx3;
    float* h3;
    cudaGetSymbolAddress((void**)&zx1, g_zx1);
    cudaGetSymbolAddress((void**)&h1,  g_h1);
    cudaGetSymbolAddress((void**)&zx2, g_zx2);
    cudaGetSymbolAddress((void**)&h2,  g_h2);
    cudaGetSymbolAddress((void**)&zx3, g_zx3);
    cudaGetSymbolAddress((void**)&h3,  g_h3);

    proj_gemm_tc<64, 512, true ><<<dim3(1024, 4), 256>>>(x,  W1, zx1);
    lstm1_rec<<<128, 256>>>(zx1, Uw1, b1, h1);

    proj_gemm_tc<128, 256, false><<<dim3(1024, 2), 256>>>(h1, W2, zx2);
    lstm64_rec<true ><<<128, 256>>>(zx2, Uw2, b2, h2);

    proj_gemm_tc<64, 256, false><<<dim3(1024, 2), 256>>>(h2, W3, zx3);
    lstm64_rec<false><<<128, 256>>>(zx3, Uw3, b3, h3);

    dense_kernel<<<1, 256>>>(h3, Wd1, bd1, Wd2, bd2, (float*)d_out);
}

// round 10
// speedup vs baseline: 1.6232x; 1.0772x over previous
#include <cuda_runtime.h>
#include <cuda_fp16.h>
#include <mma.h>

#define BB 256
#define TT 512

typedef unsigned long long ull;
using namespace nvcuda;

// ---------------- packed-math helpers ----------------
__device__ __forceinline__ void ffma2(ull& d, ull a, ull b) {
    asm("fma.rn.f32x2 %0, %1, %2, %0;" : "+l"(d) : "l"(a), "l"(b));
}
__device__ __forceinline__ ull pack2(float x, float y) {
    ull r; asm("mov.b64 %0, {%1, %2};" : "=l"(r) : "f"(x), "f"(y)); return r;
}
__device__ __forceinline__ float2 unpk2(ull v) {
    float2 f; asm("mov.b64 {%0, %1}, %2;" : "=f"(f.x), "=f"(f.y) : "l"(v)); return f;
}
__device__ __forceinline__ ull addx2(ull a, ull b) {
    ull r; asm("add.rn.f32x2 %0, %1, %2;" : "=l"(r) : "l"(a), "l"(b)); return r;
}
__device__ __forceinline__ float sigf(float x) {
    float t;
    asm("tanh.approx.f32 %0, %1;" : "=f"(t) : "f"(0.5f * x));
    return fmaf(t, 0.5f, 0.5f);
}
__device__ __forceinline__ void quad_select(
    int g, float zm, float p1, float rv, float p2,
    float& zi, float& zf, float& zg, float& zo)
{
    bool lo = (g & 1) != 0;
    bool hi = (g & 2) != 0;
    zi = hi ? (lo ? p2 : rv) : (lo ? p1 : zm);
    zf = hi ? (lo ? rv : p2) : (lo ? zm : p1);
    zg = hi ? (lo ? p1 : zm) : (lo ? p2 : rv);
    zo = hi ? (lo ? zm : p1) : (lo ? rv : p2);
}

// ---------------- device scratch ----------------
__device__ float g_zx1[TT * BB * 512];
__device__ float g_h1 [TT * BB * 128];
__device__ float g_zx2[TT * BB * 256];
__device__ float g_h2 [TT * BB * 64];
__device__ float g_zx3[TT * BB * 256];
__device__ float g_h3 [BB * 64];

// ---------------------------------------------------------------------------
// Tensor-core projection GEMM via wmma (unchanged from R9 — verified).
// ---------------------------------------------------------------------------
template<int K, int N, bool GATHER>
__global__ __launch_bounds__(256) void proj_gemm_tc(
    const float* __restrict__ A, const float* __restrict__ W,
    float* __restrict__ C)
{
    const int BM = 128;
    const int BK = 32;
    const int ALD = 48;
    const int WLD = 144;

    __shared__ __align__(32) __half As_hi[128 * 48];
    __shared__ __align__(32) __half As_lo[128 * 48];
    __shared__ __align__(32) __half Ws_hi[32 * 144];
    __shared__ __align__(32) __half Ws_lo[32 * 144];

    const int tid  = threadIdx.x;
    const int warp = tid >> 5;
    const int wm   = (warp & 1) * 64;
    const int wn   = (warp >> 1) * 32;
    const int m0   = blockIdx.x * BM;
    const int n0   = blockIdx.y * 128;

    const int arow = tid >> 1;
    const int acol = (tid & 1) * 16;
    const float* a_src;
    {
        int mrow = m0 + arow;
        if (GATHER) {
            int b = mrow & (BB - 1);
            int t = mrow >> 8;
            a_src = A + ((long)b * TT + t) * K;
        } else {
            a_src = A + (long)mrow * K;
        }
    }
    const int wrow = tid >> 3;
    const int wcol = (tid & 7) * 16;

    wmma::fragment<wmma::accumulator, 16, 16, 16, float> acc[4][2];
#pragma unroll
    for (int mi = 0; mi < 4; mi++) {
#pragma unroll
        for (int ni = 0; ni < 2; ni++) {
            wmma::fill_fragment(acc[mi][ni], 0.0f);
        }
    }

    for (int kt = 0; kt < K; kt += BK) {
#pragma unroll
        for (int i4 = 0; i4 < 4; i4++) {
            float4 v = *reinterpret_cast<const float4*>(a_src + kt + acol + i4 * 4);
            float vv[4];
            vv[0] = v.x; vv[1] = v.y; vv[2] = v.z; vv[3] = v.w;
#pragma unroll
            for (int e = 0; e < 4; e++) {
                __half h = __float2half_rn(vv[e]);
                __half l = __float2half_rn(vv[e] - __half2float(h));
                As_hi[arow * ALD + acol + i4 * 4 + e] = h;
                As_lo[arow * ALD + acol + i4 * 4 + e] = l;
            }
        }
#pragma unroll
        for (int i4 = 0; i4 < 4; i4++) {
            float4 v = *reinterpret_cast<const float4*>(
                W + (long)(kt + wrow) * N + n0 + wcol + i4 * 4);
            float vv[4];
            vv[0] = v.x; vv[1] = v.y; vv[2] = v.z; vv[3] = v.w;
#pragma unroll
            for (int e = 0; e < 4; e++) {
                __half h = __float2half_rn(vv[e]);
                __half l = __float2half_rn(vv[e] - __half2float(h));
                Ws_hi[wrow * WLD + wcol + i4 * 4 + e] = h;
                Ws_lo[wrow * WLD + wcol + i4 * 4 + e] = l;
            }
        }
        __syncthreads();

#pragma unroll
        for (int k16 = 0; k16 < BK / 16; k16++) {
            const int k0 = k16 * 16;
            wmma::fragment<wmma::matrix_a, 16, 16, 16, __half, wmma::row_major> ah[4];
            wmma::fragment<wmma::matrix_a, 16, 16, 16, __half, wmma::row_major> al[4];
            wmma::fragment<wmma::matrix_b, 16, 16, 16, __half, wmma::row_major> bh[2];
            wmma::fragment<wmma::matrix_b, 16, 16, 16, __half, wmma::row_major> bl[2];
#pragma unroll
            for (int mi = 0; mi < 4; mi++) {
                wmma::load_matrix_sync(ah[mi], &As_hi[(wm + mi * 16) * ALD + k0], ALD);
                wmma::load_matrix_sync(al[mi], &As_lo[(wm + mi * 16) * ALD + k0], ALD);
            }
#pragma unroll
            for (int ni = 0; ni < 2; ni++) {
                wmma::load_matrix_sync(bh[ni], &Ws_hi[k0 * WLD + wn + ni * 16], WLD);
                wmma::load_matrix_sync(bl[ni], &Ws_lo[k0 * WLD + wn + ni * 16], WLD);
            }
#pragma unroll
            for (int mi = 0; mi < 4; mi++) {
#pragma unroll
                for (int ni = 0; ni < 2; ni++) {
                    wmma::mma_sync(acc[mi][ni], ah[mi], bh[ni], acc[mi][ni]);
                    wmma::mma_sync(acc[mi][ni], al[mi], bh[ni], acc[mi][ni]);
                    wmma::mma_sync(acc[mi][ni], ah[mi], bl[ni], acc[mi][ni]);
                }
            }
        }
        __syncthreads();
    }

#pragma unroll
    for (int mi = 0; mi < 4; mi++) {
#pragma unroll
        for (int ni = 0; ni < 2; ni++) {
            float* dst = C + (long)(m0 + wm + mi * 16) * N + n0 + wn + ni * 16;
            wmma::store_matrix_sync(dst, acc[mi][ni], N, wmma::mem_row_major);
        }
    }
}

// ---------------------------------------------------------------------------
// Layer-2/3 recurrence: U=64, G=256. 256 CTAs x 128 threads, ONE row per CTA.
// Two independent CTAs co-reside per SM -> barrier stalls of one are covered
// by the other. Thread: g = tid&3, j = tid>>2 (0..31); owns cols g*64+j and
// g*64+j+32. Lanes g<2 combine unit j, lanes g>=2 combine unit j+32.
// ---------------------------------------------------------------------------
template<bool WRITE_ALL>
__global__ __launch_bounds__(128) void lstm64_rec(
    const float* __restrict__ zx,
    const float* __restrict__ Uw,
    const float* __restrict__ bias,
    float* __restrict__ h_out)
{
    const int U = 64;
    const int G = 256;
    const int PF = 4;
    const long ZSTRIDE = (long)BB * G;
    __shared__ float h_s[2][64];

    const int tid = threadIdx.x;
    const int row = blockIdx.x;
    const int g   = tid & 3;
    const int j   = tid >> 2;            // 0..31
    const int cA  = g * U + j;
    const int cB  = g * U + j + 32;
    const int unit = j + ((g & 2) << 4); // j or j+32
    const bool useB = (g & 2) != 0;

    ull wA[32];
    ull wB[32];
#pragma unroll
    for (int k2 = 0; k2 < 32; k2++) {
        wA[k2] = pack2(Uw[(2 * k2) * G + cA], Uw[(2 * k2 + 1) * G + cA]);
        wB[k2] = pack2(Uw[(2 * k2) * G + cB], Uw[(2 * k2 + 1) * G + cB]);
    }
    (&h_s[0][0])[tid] = 0.f;             // zero both buffers (128 floats)
    const float bzA = bias[cA];
    const float bzB = bias[cB];
    __syncthreads();

    const float* zpA = zx + (long)row * G + cA;
    const float* zpB = zx + (long)row * G + cB;

    float creg = 0.f;
    float zAr[4];
    float zBr[4];
#pragma unroll
    for (int p = 0; p < PF; p++) {
        zAr[p] = zpA[(long)p * ZSTRIDE];
        zBr[p] = zpB[(long)p * ZSTRIDE];
    }

    int cur = 0;
#pragma unroll 4
    for (int t = 0; t < TT; t++) {
        const int s = t & (PF - 1);
        float zA = zAr[s] + bzA;
        float zB = zBr[s] + bzB;
        if (t + PF < TT) {
            zAr[s] = zpA[(long)(t + PF) * ZSTRIDE];
            zBr[s] = zpB[(long)(t + PF) * ZSTRIDE];
        }

        ull aA0 = 0ull;
        ull aA1 = 0ull;
        ull aB0 = 0ull;
        ull aB1 = 0ull;
        const ulonglong2* hp = reinterpret_cast<const ulonglong2*>(&h_s[cur][0]);
#pragma unroll
        for (int k4 = 0; k4 < 16; k4++) {
            ulonglong2 hh = hp[k4];
            ffma2(aA0, wA[2 * k4],     hh.x);
            ffma2(aA1, wA[2 * k4 + 1], hh.y);
            ffma2(aB0, wB[2 * k4],     hh.x);
            ffma2(aB1, wB[2 * k4 + 1], hh.y);
        }
        float2 fA = unpk2(addx2(aA0, aA1));
        float2 fB = unpk2(addx2(aB0, aB1));
        zA += fA.x + fA.y;
        zB += fB.x + fB.y;

        // independent butterflies within the quad
        float sA1 = __shfl_xor_sync(0xffffffffu, zA, 1);
        float sA2 = __shfl_xor_sync(0xffffffffu, zA, 2);
        float sA3 = __shfl_xor_sync(0xffffffffu, zA, 3);
        float sB1 = __shfl_xor_sync(0xffffffffu, zB, 1);
        float sB2 = __shfl_xor_sync(0xffffffffu, zB, 2);
        float sB3 = __shfl_xor_sync(0xffffffffu, zB, 3);

        float mine = useB ? zB  : zA;
        float p1   = useB ? sB1 : sA1;
        float rv   = useB ? sB2 : sA2;
        float p2   = useB ? sB3 : sA3;

        float zi, zf, zg_, zoo;
        quad_select(g, mine, p1, rv, p2, zi, zf, zg_, zoo);

        float ig = sigf(zi);
        float fg = sigf(zf);
        float gg = fmaxf(zg_, 0.f);
        float og = sigf(zoo);
        creg = fg * creg + ig * gg;
        float h = og * fmaxf(creg, 0.f);

        if ((g & 1) == 0) {              // lanes g=0 (unit j) and g=2 (unit j+32)
            h_s[cur ^ 1][unit] = h;
            if (WRITE_ALL) {
                h_out[((long)t * BB + row) * U + unit] = h;
            } else if (t == TT - 1) {
                h_out[(long)row * U + unit] = h;
            }
        }
        __syncthreads();
        cur ^= 1;
    }
}

// ---------------------------------------------------------------------------
// Layer-1 recurrence (unchanged from R9 — verified).
// ---------------------------------------------------------------------------
__global__ __launch_bounds__(256) void lstm1_rec(
    const float* __restrict__ zx,
    const float* __restrict__ Uw,
    const float* __restrict__ bias,
    float* __restrict__ h_out)
{
    const int U = 128;
    const int G = 512;
    const int PF = 4;
    const long ZSTRIDE = (long)BB * G;
    __shared__ __half h_s[2][2][128];

    const int tid = threadIdx.x;
    const int b0  = blockIdx.x * 2;
    const int g   = tid & 3;
    const int j0  = tid >> 2;
    const int c0  = g * U + j0;
    const int c1  = g * U + j0 + 64;
    const int myrow = (g >> 1) & 1;

    half2 w0[64];
    half2 w1[64];
#pragma unroll
    for (int k2 = 0; k2 < 64; k2++) {
        w0[k2] = __floats2half2_rn(Uw[(2 * k2) * G + c0], Uw[(2 * k2 + 1) * G + c0]);
        w1[k2] = __floats2half2_rn(Uw[(2 * k2) * G + c1], Uw[(2 * k2 + 1) * G + c1]);
    }
    for (int i = tid; i < 512; i += 256) {
        (&h_s[0][0][0])[i] = __float2half_rn(0.f);
    }
    const float bz0 = bias[c0];
    const float bz1 = bias[c1];
    __syncthreads();

    const float* z00p = zx + (long)b0 * G + c0;
    const float* z01p = z00p + G;
    const float* z10p = zx + (long)b0 * G + c1;
    const float* z11p = z10p + G;

    float c_a = 0.f;
    float c_b = 0.f;
    float zA0[4];
    float zA1[4];
    float zB0[4];
    float zB1[4];
#pragma unroll
    for (int p = 0; p < PF; p++) {
        zA0[p] = z00p[(long)p * ZSTRIDE];
        zA1[p] = z01p[(long)p * ZSTRIDE];
        zB0[p] = z10p[(long)p * ZSTRIDE];
        zB1[p] = z11p[(long)p * ZSTRIDE];
    }

    int cur = 0;
#pragma unroll 4
    for (int t = 0; t < TT; t++) {
        const int s = t & (PF - 1);
        float a00 = zA0[s] + bz0;
        float a01 = zA1[s] + bz0;
        float a10 = zB0[s] + bz1;
        float a11 = zB1[s] + bz1;
        if (t + PF < TT) {
            zA0[s] = z00p[(long)(t + PF) * ZSTRIDE];
            zA1[s] = z01p[(long)(t + PF) * ZSTRIDE];
            zB0[s] = z10p[(long)(t + PF) * ZSTRIDE];
            zB1[s] = z11p[(long)(t + PF) * ZSTRIDE];
        }

#pragma unroll
        for (int kb = 0; kb < 4; kb++) {
            half2 s00 = __floats2half2_rn(0.f, 0.f);
            half2 s01 = __floats2half2_rn(0.f, 0.f);
            half2 s10 = __floats2half2_rn(0.f, 0.f);
            half2 s11 = __floats2half2_rn(0.f, 0.f);
#pragma unroll
            for (int k8 = 0; k8 < 4; k8++) {
                const int kbase = kb * 32 + k8 * 8;
                uint4 hv0 = *reinterpret_cast<const uint4*>(&h_s[cur][0][kbase]);
                uint4 hv1 = *reinterpret_cast<const uint4*>(&h_s[cur][1][kbase]);
                const half2* hp0 = reinterpret_cast<const half2*>(&hv0);
                const half2* hp1 = reinterpret_cast<const half2*>(&hv1);
#pragma unroll
                for (int q = 0; q < 4; q++) {
                    const int k2 = kbase / 2 + q;
                    s00 = __hfma2(w0[k2], hp0[q], s00);
                    s01 = __hfma2(w0[k2], hp1[q], s01);
                    s10 = __hfma2(w1[k2], hp0[q], s10);
                    s11 = __hfma2(w1[k2], hp1[q], s11);
                }
            }
            float2 fa = __half22float2(s00);
            float2 fb = __half22float2(s01);
            float2 fc = __half22float2(s10);
            float2 fd = __half22float2(s11);
            a00 += fa.x + fa.y;
            a01 += fb.x + fb.y;
            a10 += fc.x + fc.y;
            a11 += fd.x + fd.y;
        }

        float mineA  = myrow ? a01 : a00;
        float otherA = myrow ? a00 : a01;
        float mineB  = myrow ? a11 : a10;
        float otherB = myrow ? a10 : a11;
        float p1A = __shfl_xor_sync(0xffffffffu, mineA,  1);
        float rvA = __shfl_xor_sync(0xffffffffu, otherA, 2);
        float p2A = __shfl_xor_sync(0xffffffffu, otherA, 3);
        float p1B = __shfl_xor_sync(0xffffffffu, mineB,  1);
        float rvB = __shfl_xor_sync(0xffffffffu, otherB, 2);
        float p2B = __shfl_xor_sync(0xffffffffu, otherB, 3);

        float zi, zf, zg_, zoo;
        quad_select(g, mineA, p1A, rvA, p2A, zi, zf, zg_, zoo);
        float ig = sigf(zi);
        float fg = sigf(zf);
        float og = sigf(zoo);
        c_a = fg * c_a + ig * fmaxf(zg_, 0.f);
        float hA = og * fmaxf(c_a, 0.f);

        quad_select(g, mineB, p1B, rvB, p2B, zi, zf, zg_, zoo);
        ig = sigf(zi);
        fg = sigf(zf);
        og = sigf(zoo);
        c_b = fg * c_b + ig * fmaxf(zg_, 0.f);
        float hB = og * fmaxf(c_b, 0.f);

        if ((g & 1) == 0) {
            h_s[cur ^ 1][myrow][j0]      = __float2half_rn(hA);
            h_s[cur ^ 1][myrow][j0 + 64] = __float2half_rn(hB);
            float* ho = h_out + ((long)t * BB + b0 + myrow) * U;
            ho[j0]      = hA;
            ho[j0 + 64] = hB;
        }
        __syncthreads();
        cur ^= 1;
    }
}

// ---------------- dense head ----------------
__global__ __launch_bounds__(256) void dense_kernel(
    const float* __restrict__ h3, const float* __restrict__ Wd1,
    const float* __restrict__ bd1, const float* __restrict__ Wd2,
    const float* __restrict__ bd2, float* __restrict__ out)
{
    __shared__ float w1[64 * 32];
    __shared__ float w2[32];
    __shared__ float b1s[32];
    const int tid = threadIdx.x;
    for (int i = tid; i < 64 * 32; i += 256) {
        w1[i] = Wd1[i];
    }
    if (tid < 32) {
        w2[tid] = Wd2[tid];
        b1s[tid] = bd1[tid];
    }
    __syncthreads();

    float hr[64];
#pragma unroll
    for (int k4 = 0; k4 < 16; k4++) {
        *reinterpret_cast<float4*>(&hr[4 * k4]) =
            *reinterpret_cast<const float4*>(&h3[tid * 64 + 4 * k4]);
    }

    float o = bd2[0];
#pragma unroll 4
    for (int jj = 0; jj < 32; jj++) {
        float d = b1s[jj];
#pragma unroll
        for (int k = 0; k < 64; k++) {
            d += hr[k] * w1[k * 32 + jj];
        }
        o += fmaxf(d, 0.f) * w2[jj];
    }
    out[tid] = o;
}

// ---------------- launcher ----------------
extern "C" void kernel_launch(void* const* d_in, const int* in_sizes, int n_in,
                              void* d_out, int out_size)
{
    const float* x   = (const float*)d_in[0];
    const float* W1  = (const float*)d_in[1];
    const float* Uw1 = (const float*)d_in[2];
    const float* b1  = (const float*)d_in[3];
    const float* W2  = (const float*)d_in[4];
    const float* Uw2 = (const float*)d_in[5];
    const float* b2  = (const float*)d_in[6];
    const float* W3  = (const float*)d_in[7];
    const float* Uw3 = (const float*)d_in[8];
    const float* b3  = (const float*)d_in[9];
    const float* Wd1 = (const float*)d_in[10];
    const float* bd1 = (const float*)d_in[11];
    const float* Wd2 = (const float*)d_in[12];
    const float* bd2 = (const float*)d_in[13];

    float* zx1;
    float* h1;
    float* zx2;
    float* h2;
    float* zx3;
    float* h3;
    cudaGetSymbolAddress((void**)&zx1, g_zx1);
    cudaGetSymbolAddress((void**)&h1,  g_h1);
    cudaGetSymbolAddress((void**)&zx2, g_zx2);
    cudaGetSymbolAddress((void**)&h2,  g_h2);
    cudaGetSymbolAddress((void**)&zx3, g_zx3);
    cudaGetSymbolAddress((void**)&h3,  g_h3);

    proj_gemm_tc<64, 512, true ><<<dim3(1024, 4), 256>>>(x,  W1, zx1);
    lstm1_rec<<<128, 256>>>(zx1, Uw1, b1, h1);

    proj_gemm_tc<128, 256, false><<<dim3(1024, 2), 256>>>(h1, W2, zx2);
    lstm64_rec<true ><<<256, 128>>>(zx2, Uw2, b2, h2);

    proj_gemm_tc<64, 256, false><<<dim3(1024, 2), 256>>>(h2, W3, zx3);
    lstm64_rec<false><<<256, 128>>>(zx3, Uw3, b3, h3);

    dense_kernel<<<1, 256>>>(h3, Wd1, bd1, Wd2, bd2, (float*)d_out);
}

// round 11
// speedup vs baseline: 1.6700x; 1.0289x over previous
#include <cuda_runtime.h>
#include <cuda_fp16.h>
#include <mma.h>

#define BB 256
#define TT 512

typedef unsigned long long ull;
using namespace nvcuda;

// ---------------- packed-math helpers ----------------
__device__ __forceinline__ void ffma2(ull& d, ull a, ull b) {
    asm("fma.rn.f32x2 %0, %1, %2, %0;" : "+l"(d) : "l"(a), "l"(b));
}
__device__ __forceinline__ ull pack2(float x, float y) {
    ull r; asm("mov.b64 %0, {%1, %2};" : "=l"(r) : "f"(x), "f"(y)); return r;
}
__device__ __forceinline__ float2 unpk2(ull v) {
    float2 f; asm("mov.b64 {%0, %1}, %2;" : "=f"(f.x), "=f"(f.y) : "l"(v)); return f;
}
__device__ __forceinline__ ull addx2(ull a, ull b) {
    ull r; asm("add.rn.f32x2 %0, %1, %2;" : "=l"(r) : "l"(a), "l"(b)); return r;
}
__device__ __forceinline__ float sigf(float x) {
    float t;
    asm("tanh.approx.f32 %0, %1;" : "=f"(t) : "f"(0.5f * x));
    return fmaf(t, 0.5f, 0.5f);
}
__device__ __forceinline__ void quad_select(
    int g, float zm, float p1, float rv, float p2,
    float& zi, float& zf, float& zg, float& zo)
{
    bool lo = (g & 1) != 0;
    bool hi = (g & 2) != 0;
    zi = hi ? (lo ? p2 : rv) : (lo ? p1 : zm);
    zf = hi ? (lo ? rv : p2) : (lo ? zm : p1);
    zg = hi ? (lo ? p1 : zm) : (lo ? p2 : rv);
    zo = hi ? (lo ? zm : p1) : (lo ? rv : p2);
}

// ---------------- device scratch ----------------
__device__ float g_zx1[TT * BB * 512];
__device__ float g_h1 [TT * BB * 128];
__device__ float g_zx2[TT * BB * 256];
__device__ float g_h2 [TT * BB * 64];
__device__ float g_zx3[TT * BB * 256];
__device__ float g_h3 [BB * 64];

// ---------------------------------------------------------------------------
// Tensor-core projection GEMM via wmma (unchanged from R9/R10 — verified).
// ---------------------------------------------------------------------------
template<int K, int N, bool GATHER>
__global__ __launch_bounds__(256) void proj_gemm_tc(
    const float* __restrict__ A, const float* __restrict__ W,
    float* __restrict__ C)
{
    const int BM = 128;
    const int BK = 32;
    const int ALD = 48;
    const int WLD = 144;

    __shared__ __align__(32) __half As_hi[128 * 48];
    __shared__ __align__(32) __half As_lo[128 * 48];
    __shared__ __align__(32) __half Ws_hi[32 * 144];
    __shared__ __align__(32) __half Ws_lo[32 * 144];

    const int tid  = threadIdx.x;
    const int warp = tid >> 5;
    const int wm   = (warp & 1) * 64;
    const int wn   = (warp >> 1) * 32;
    const int m0   = blockIdx.x * BM;
    const int n0   = blockIdx.y * 128;

    const int arow = tid >> 1;
    const int acol = (tid & 1) * 16;
    const float* a_src;
    {
        int mrow = m0 + arow;
        if (GATHER) {
            int b = mrow & (BB - 1);
            int t = mrow >> 8;
            a_src = A + ((long)b * TT + t) * K;
        } else {
            a_src = A + (long)mrow * K;
        }
    }
    const int wrow = tid >> 3;
    const int wcol = (tid & 7) * 16;

    wmma::fragment<wmma::accumulator, 16, 16, 16, float> acc[4][2];
#pragma unroll
    for (int mi = 0; mi < 4; mi++) {
#pragma unroll
        for (int ni = 0; ni < 2; ni++) {
            wmma::fill_fragment(acc[mi][ni], 0.0f);
        }
    }

    for (int kt = 0; kt < K; kt += BK) {
#pragma unroll
        for (int i4 = 0; i4 < 4; i4++) {
            float4 v = *reinterpret_cast<const float4*>(a_src + kt + acol + i4 * 4);
            float vv[4];
            vv[0] = v.x; vv[1] = v.y; vv[2] = v.z; vv[3] = v.w;
#pragma unroll
            for (int e = 0; e < 4; e++) {
                __half h = __float2half_rn(vv[e]);
                __half l = __float2half_rn(vv[e] - __half2float(h));
                As_hi[arow * ALD + acol + i4 * 4 + e] = h;
                As_lo[arow * ALD + acol + i4 * 4 + e] = l;
            }
        }
#pragma unroll
        for (int i4 = 0; i4 < 4; i4++) {
            float4 v = *reinterpret_cast<const float4*>(
                W + (long)(kt + wrow) * N + n0 + wcol + i4 * 4);
            float vv[4];
            vv[0] = v.x; vv[1] = v.y; vv[2] = v.z; vv[3] = v.w;
#pragma unroll
            for (int e = 0; e < 4; e++) {
                __half h = __float2half_rn(vv[e]);
                __half l = __float2half_rn(vv[e] - __half2float(h));
                Ws_hi[wrow * WLD + wcol + i4 * 4 + e] = h;
                Ws_lo[wrow * WLD + wcol + i4 * 4 + e] = l;
            }
        }
        __syncthreads();

#pragma unroll
        for (int k16 = 0; k16 < BK / 16; k16++) {
            const int k0 = k16 * 16;
            wmma::fragment<wmma::matrix_a, 16, 16, 16, __half, wmma::row_major> ah[4];
            wmma::fragment<wmma::matrix_a, 16, 16, 16, __half, wmma::row_major> al[4];
            wmma::fragment<wmma::matrix_b, 16, 16, 16, __half, wmma::row_major> bh[2];
            wmma::fragment<wmma::matrix_b, 16, 16, 16, __half, wmma::row_major> bl[2];
#pragma unroll
            for (int mi = 0; mi < 4; mi++) {
                wmma::load_matrix_sync(ah[mi], &As_hi[(wm + mi * 16) * ALD + k0], ALD);
                wmma::load_matrix_sync(al[mi], &As_lo[(wm + mi * 16) * ALD + k0], ALD);
            }
#pragma unroll
            for (int ni = 0; ni < 2; ni++) {
                wmma::load_matrix_sync(bh[ni], &Ws_hi[k0 * WLD + wn + ni * 16], WLD);
                wmma::load_matrix_sync(bl[ni], &Ws_lo[k0 * WLD + wn + ni * 16], WLD);
            }
#pragma unroll
            for (int mi = 0; mi < 4; mi++) {
#pragma unroll
                for (int ni = 0; ni < 2; ni++) {
                    wmma::mma_sync(acc[mi][ni], ah[mi], bh[ni], acc[mi][ni]);
                    wmma::mma_sync(acc[mi][ni], al[mi], bh[ni], acc[mi][ni]);
                    wmma::mma_sync(acc[mi][ni], ah[mi], bl[ni], acc[mi][ni]);
                }
            }
        }
        __syncthreads();
    }

#pragma unroll
    for (int mi = 0; mi < 4; mi++) {
#pragma unroll
        for (int ni = 0; ni < 2; ni++) {
            float* dst = C + (long)(m0 + wm + mi * 16) * N + n0 + wn + ni * 16;
            wmma::store_matrix_sync(dst, acc[mi][ni], N, wmma::mem_row_major);
        }
    }
}

// ---------------------------------------------------------------------------
// Layer-2/3 recurrence: U=64, G=256. 256 CTAs x 128 threads, ONE row per CTA
// (R10 structure) with fp16 weights in registers + fp16 h in smem + HFMA2
// accumulation in 16-k groups flushed to fp32.
// Thread: g = tid&3, j = tid>>2 (0..31); owns cols g*64+j and g*64+j+32.
// ---------------------------------------------------------------------------
template<bool WRITE_ALL>
__global__ __launch_bounds__(128) void lstm64_rec(
    const float* __restrict__ zx,
    const float* __restrict__ Uw,
    const float* __restrict__ bias,
    float* __restrict__ h_out)
{
    const int U = 64;
    const int G = 256;
    const int PF = 4;
    const long ZSTRIDE = (long)BB * G;
    __shared__ __align__(16) __half h_s[2][64];

    const int tid = threadIdx.x;
    const int row = blockIdx.x;
    const int g   = tid & 3;
    const int j   = tid >> 2;            // 0..31
    const int cA  = g * U + j;
    const int cB  = g * U + j + 32;
    const int unit = j + ((g & 2) << 4); // j or j+32
    const bool useB = (g & 2) != 0;

    half2 wA[32];
    half2 wB[32];
#pragma unroll
    for (int k2 = 0; k2 < 32; k2++) {
        wA[k2] = __floats2half2_rn(Uw[(2 * k2) * G + cA], Uw[(2 * k2 + 1) * G + cA]);
        wB[k2] = __floats2half2_rn(Uw[(2 * k2) * G + cB], Uw[(2 * k2 + 1) * G + cB]);
    }
    (&h_s[0][0])[tid] = __float2half_rn(0.f);   // zero both buffers (128 halves)
    const float bzA = bias[cA];
    const float bzB = bias[cB];
    __syncthreads();

    const float* zpA = zx + (long)row * G + cA;
    const float* zpB = zx + (long)row * G + cB;

    float creg = 0.f;
    float zAr[4];
    float zBr[4];
#pragma unroll
    for (int p = 0; p < PF; p++) {
        zAr[p] = zpA[(long)p * ZSTRIDE];
        zBr[p] = zpB[(long)p * ZSTRIDE];
    }

    int cur = 0;
#pragma unroll 4
    for (int t = 0; t < TT; t++) {
        const int s = t & (PF - 1);
        float zA = zAr[s] + bzA;
        float zB = zBr[s] + bzB;
        if (t + PF < TT) {
            zAr[s] = zpA[(long)(t + PF) * ZSTRIDE];
            zBr[s] = zpB[(long)(t + PF) * ZSTRIDE];
        }

        // load full h row (64 halves = 8 x uint4), broadcast across lanes
        uint4 hbuf[8];
        const uint4* hsp = reinterpret_cast<const uint4*>(&h_s[cur][0]);
#pragma unroll
        for (int i = 0; i < 8; i++) {
            hbuf[i] = hsp[i];
        }
        const half2* hp = reinterpret_cast<const half2*>(hbuf);

        // 4 groups of 16 k; fp16 partial sums flushed to fp32 per group
#pragma unroll
        for (int grp = 0; grp < 4; grp++) {
            half2 sA = __floats2half2_rn(0.f, 0.f);
            half2 sB = __floats2half2_rn(0.f, 0.f);
#pragma unroll
            for (int q = 0; q < 8; q++) {
                const int k2 = grp * 8 + q;
                sA = __hfma2(wA[k2], hp[k2], sA);
                sB = __hfma2(wB[k2], hp[k2], sB);
            }
            float2 fA = __half22float2(sA);
            float2 fB = __half22float2(sB);
            zA += fA.x + fA.y;
            zB += fB.x + fB.y;
        }

        // independent butterflies within the quad
        float sA1 = __shfl_xor_sync(0xffffffffu, zA, 1);
        float sA2 = __shfl_xor_sync(0xffffffffu, zA, 2);
        float sA3 = __shfl_xor_sync(0xffffffffu, zA, 3);
        float sB1 = __shfl_xor_sync(0xffffffffu, zB, 1);
        float sB2 = __shfl_xor_sync(0xffffffffu, zB, 2);
        float sB3 = __shfl_xor_sync(0xffffffffu, zB, 3);

        float mine = useB ? zB  : zA;
        float p1   = useB ? sB1 : sA1;
        float rv   = useB ? sB2 : sA2;
        float p2   = useB ? sB3 : sA3;

        float zi, zf, zg_, zoo;
        quad_select(g, mine, p1, rv, p2, zi, zf, zg_, zoo);

        float ig = sigf(zi);
        float fg = sigf(zf);
        float gg = fmaxf(zg_, 0.f);
        float og = sigf(zoo);
        creg = fg * creg + ig * gg;
        float h = og * fmaxf(creg, 0.f);

        if ((g & 1) == 0) {              // lanes g=0 (unit j) and g=2 (unit j+32)
            h_s[cur ^ 1][unit] = __float2half_rn(h);
            if (WRITE_ALL) {
                h_out[((long)t * BB + row) * U + unit] = h;
            } else if (t == TT - 1) {
                h_out[(long)row * U + unit] = h;
            }
        }
        __syncthreads();
        cur ^= 1;
    }
}

// ---------------------------------------------------------------------------
// Layer-1 recurrence (unchanged from R9/R10 — verified).
// ---------------------------------------------------------------------------
__global__ __launch_bounds__(256) void lstm1_rec(
    const float* __restrict__ zx,
    const float* __restrict__ Uw,
    const float* __restrict__ bias,
    float* __restrict__ h_out)
{
    const int U = 128;
    const int G = 512;
    const int PF = 4;
    const long ZSTRIDE = (long)BB * G;
    __shared__ __half h_s[2][2][128];

    const int tid = threadIdx.x;
    const int b0  = blockIdx.x * 2;
    const int g   = tid & 3;
    const int j0  = tid >> 2;
    const int c0  = g * U + j0;
    const int c1  = g * U + j0 + 64;
    const int myrow = (g >> 1) & 1;

    half2 w0[64];
    half2 w1[64];
#pragma unroll
    for (int k2 = 0; k2 < 64; k2++) {
        w0[k2] = __floats2half2_rn(Uw[(2 * k2) * G + c0], Uw[(2 * k2 + 1) * G + c0]);
        w1[k2] = __floats2half2_rn(Uw[(2 * k2) * G + c1], Uw[(2 * k2 + 1) * G + c1]);
    }
    for (int i = tid; i < 512; i += 256) {
        (&h_s[0][0][0])[i] = __float2half_rn(0.f);
    }
    const float bz0 = bias[c0];
    const float bz1 = bias[c1];
    __syncthreads();

    const float* z00p = zx + (long)b0 * G + c0;
    const float* z01p = z00p + G;
    const float* z10p = zx + (long)b0 * G + c1;
    const float* z11p = z10p + G;

    float c_a = 0.f;
    float c_b = 0.f;
    float zA0[4];
    float zA1[4];
    float zB0[4];
    float zB1[4];
#pragma unroll
    for (int p = 0; p < PF; p++) {
        zA0[p] = z00p[(long)p * ZSTRIDE];
        zA1[p] = z01p[(long)p * ZSTRIDE];
        zB0[p] = z10p[(long)p * ZSTRIDE];
        zB1[p] = z11p[(long)p * ZSTRIDE];
    }

    int cur = 0;
#pragma unroll 4
    for (int t = 0; t < TT; t++) {
        const int s = t & (PF - 1);
        float a00 = zA0[s] + bz0;
        float a01 = zA1[s] + bz0;
        float a10 = zB0[s] + bz1;
        float a11 = zB1[s] + bz1;
        if (t + PF < TT) {
            zA0[s] = z00p[(long)(t + PF) * ZSTRIDE];
            zA1[s] = z01p[(long)(t + PF) * ZSTRIDE];
            zB0[s] = z10p[(long)(t + PF) * ZSTRIDE];
            zB1[s] = z11p[(long)(t + PF) * ZSTRIDE];
        }

#pragma unroll
        for (int kb = 0; kb < 4; kb++) {
            half2 s00 = __floats2half2_rn(0.f, 0.f);
            half2 s01 = __floats2half2_rn(0.f, 0.f);
            half2 s10 = __floats2half2_rn(0.f, 0.f);
            half2 s11 = __floats2half2_rn(0.f, 0.f);
#pragma unroll
            for (int k8 = 0; k8 < 4; k8++) {
                const int kbase = kb * 32 + k8 * 8;
                uint4 hv0 = *reinterpret_cast<const uint4*>(&h_s[cur][0][kbase]);
                uint4 hv1 = *reinterpret_cast<const uint4*>(&h_s[cur][1][kbase]);
                const half2* hp0 = reinterpret_cast<const half2*>(&hv0);
                const half2* hp1 = reinterpret_cast<const half2*>(&hv1);
#pragma unroll
                for (int q = 0; q < 4; q++) {
                    const int k2 = kbase / 2 + q;
                    s00 = __hfma2(w0[k2], hp0[q], s00);
                    s01 = __hfma2(w0[k2], hp1[q], s01);
                    s10 = __hfma2(w1[k2], hp0[q], s10);
                    s11 = __hfma2(w1[k2], hp1[q], s11);
                }
            }
            float2 fa = __half22float2(s00);
            float2 fb = __half22float2(s01);
            float2 fc = __half22float2(s10);
            float2 fd = __half22float2(s11);
            a00 += fa.x + fa.y;
            a01 += fb.x + fb.y;
            a10 += fc.x + fc.y;
            a11 += fd.x + fd.y;
        }

        float mineA  = myrow ? a01 : a00;
        float otherA = myrow ? a00 : a01;
        float mineB  = myrow ? a11 : a10;
        float otherB = myrow ? a10 : a11;
        float p1A = __shfl_xor_sync(0xffffffffu, mineA,  1);
        float rvA = __shfl_xor_sync(0xffffffffu, otherA, 2);
        float p2A = __shfl_xor_sync(0xffffffffu, otherA, 3);
        float p1B = __shfl_xor_sync(0xffffffffu, mineB,  1);
        float rvB = __shfl_xor_sync(0xffffffffu, otherB, 2);
        float p2B = __shfl_xor_sync(0xffffffffu, otherB, 3);

        float zi, zf, zg_, zoo;
        quad_select(g, mineA, p1A, rvA, p2A, zi, zf, zg_, zoo);
        float ig = sigf(zi);
        float fg = sigf(zf);
        float og = sigf(zoo);
        c_a = fg * c_a + ig * fmaxf(zg_, 0.f);
        float hA = og * fmaxf(c_a, 0.f);

        quad_select(g, mineB, p1B, rvB, p2B, zi, zf, zg_, zoo);
        ig = sigf(zi);
        fg = sigf(zf);
        og = sigf(zoo);
        c_b = fg * c_b + ig * fmaxf(zg_, 0.f);
        float hB = og * fmaxf(c_b, 0.f);

        if ((g & 1) == 0) {
            h_s[cur ^ 1][myrow][j0]      = __float2half_rn(hA);
            h_s[cur ^ 1][myrow][j0 + 64] = __float2half_rn(hB);
            float* ho = h_out + ((long)t * BB + b0 + myrow) * U;
            ho[j0]      = hA;
            ho[j0 + 64] = hB;
        }
        __syncthreads();
        cur ^= 1;
    }
}

// ---------------- dense head ----------------
__global__ __launch_bounds__(256) void dense_kernel(
    const float* __restrict__ h3, const float* __restrict__ Wd1,
    const float* __restrict__ bd1, const float* __restrict__ Wd2,
    const float* __restrict__ bd2, float* __restrict__ out)
{
    __shared__ float w1[64 * 32];
    __shared__ float w2[32];
    __shared__ float b1s[32];
    const int tid = threadIdx.x;
    for (int i = tid; i < 64 * 32; i += 256) {
        w1[i] = Wd1[i];
    }
    if (tid < 32) {
        w2[tid] = Wd2[tid];
        b1s[tid] = bd1[tid];
    }
    __syncthreads();

    float hr[64];
#pragma unroll
    for (int k4 = 0; k4 < 16; k4++) {
        *reinterpret_cast<float4*>(&hr[4 * k4]) =
            *reinterpret_cast<const float4*>(&h3[tid * 64 + 4 * k4]);
    }

    float o = bd2[0];
#pragma unroll 4
    for (int jj = 0; jj < 32; jj++) {
        float d = b1s[jj];
#pragma unroll
        for (int k = 0; k < 64; k++) {
            d += hr[k] * w1[k * 32 + jj];
        }
        o += fmaxf(d, 0.f) * w2[jj];
    }
    out[tid] = o;
}

// ---------------- launcher ----------------
extern "C" void kernel_launch(void* const* d_in, const int* in_sizes, int n_in,
                              void* d_out, int out_size)
{
    const float* x   = (const float*)d_in[0];
    const float* W1  = (const float*)d_in[1];
    const float* Uw1 = (const float*)d_in[2];
    const float* b1  = (const float*)d_in[3];
    const float* W2  = (const float*)d_in[4];
    const float* Uw2 = (const float*)d_in[5];
    const float* b2  = (const float*)d_in[6];
    const float* W3  = (const float*)d_in[7];
    const float* Uw3 = (const float*)d_in[8];
    const float* b3  = (const float*)d_in[9];
    const float* Wd1 = (const float*)d_in[10];
    const float* bd1 = (const float*)d_in[11];
    const float* Wd2 = (const float*)d_in[12];
    const float* bd2 = (const float*)d_in[13];

    float* zx1;
    float* h1;
    float* zx2;
    float* h2;
    float* zx3;
    float* h3;
    cudaGetSymbolAddress((void**)&zx1, g_zx1);
    cudaGetSymbolAddress((void**)&h1,  g_h1);
    cudaGetSymbolAddress((void**)&zx2, g_zx2);
    cudaGetSymbolAddress((void**)&h2,  g_h2);
    cudaGetSymbolAddress((void**)&zx3, g_zx3);
    cudaGetSymbolAddress((void**)&h3,  g_h3);

    proj_gemm_tc<64, 512, true ><<<dim3(1024, 4), 256>>>(x,  W1, zx1);
    lstm1_rec<<<128, 256>>>(zx1, Uw1, b1, h1);

    proj_gemm_tc<128, 256, false><<<dim3(1024, 2), 256>>>(h1, W2, zx2);
    lstm64_rec<true ><<<256, 128>>>(zx2, Uw2, b2, h2);

    proj_gemm_tc<64, 256, false><<<dim3(1024, 2), 256>>>(h2, W3, zx3);
    lstm64_rec<false><<<256, 128>>>(zx3, Uw3, b3, h3);

    dense_kernel<<<1, 256>>>(h3, Wd1, bd1, Wd2, bd2, (float*)d_out);
}